// round 1
// baseline (speedup 1.0000x reference)
#include <cuda_runtime.h>

#define BB 128
#define TT 256
#define II 64
#define HH 1024
#define OO 64

// Persistent device-global state (allocation-free scratch).
// States are stored TRANSPOSED: s[k][b] at s[k*BB + b] so per-k loads coalesce.
__device__ float g_xt[TT * II * BB];     // x transposed to [t][i][b], 8 MB
__device__ float g_h1[2][HH * BB];       // ping-pong
__device__ float g_h2[2][HH * BB];       // ping-pong
__device__ float g_u[HH * BB];           // single buffer (stream-ordered)

// ---------------------------------------------------------------------------
__global__ void k_init() {
    int i = blockIdx.x * blockDim.x + threadIdx.x;
    if (i < HH * BB) {
        g_h1[0][i] = 0.f;
        g_h2[0][i] = 0.f;
        g_u[i]     = 1.f;
    }
}

// Transpose x[B][T*I] -> g_xt[T*I][B] with a 32x32 smem tile.
__global__ void k_transpose_x(const float* __restrict__ x) {
    __shared__ float tile[32][33];
    int n0 = blockIdx.x * 32;  // ti
    int m0 = blockIdx.y * 32;  // b
    int tx = threadIdx.x, ty = threadIdx.y;
    tile[ty][tx] = x[(m0 + ty) * (TT * II) + n0 + tx];
    __syncthreads();
    g_xt[(n0 + ty) * BB + m0 + tx] = tile[tx][ty];
}

// ---------------------------------------------------------------------------
// K1: h1_new = tanh(x_t @ Wih1^T + b_ih1 + h1 @ Whh1^T + b_hh1)
// grid = H/8 CTAs, block (128, 2): threadIdx.x = batch, threadIdx.y splits the
// 8 output rows in two halves of 4.
__global__ void __launch_bounds__(256) k_step1(
    const float* __restrict__ Wih1, const float* __restrict__ bih1,
    const float* __restrict__ Whh1, const float* __restrict__ bhh1,
    int t)
{
    __shared__ float sWih[8][II];
    __shared__ float sWhh[8][HH];
    int j0  = blockIdx.x * 8;
    int b   = threadIdx.x;
    int tid = threadIdx.y * 128 + threadIdx.x;

    for (int idx = tid; idx < 8 * II; idx += 256) {
        int jj = idx / II, k = idx % II;
        sWih[jj][k] = Wih1[(j0 + jj) * II + k];
    }
    for (int idx = tid; idx < 8 * HH; idx += 256) {
        int jj = idx >> 10, k = idx & 1023;
        sWhh[jj][k] = Whh1[(j0 + jj) * HH + k];
    }
    __syncthreads();

    const float* xt  = g_xt + t * II * BB;
    const float* h1p = g_h1[t & 1];
    int jy = threadIdx.y * 4;
    float acc[4] = {0.f, 0.f, 0.f, 0.f};

    #pragma unroll 8
    for (int i = 0; i < II; i++) {
        float xv = xt[i * BB + b];
        #pragma unroll
        for (int jj = 0; jj < 4; jj++) acc[jj] += xv * sWih[jy + jj][i];
    }
    #pragma unroll 8
    for (int k = 0; k < HH; k++) {
        float hv = h1p[k * BB + b];
        #pragma unroll
        for (int jj = 0; jj < 4; jj++) acc[jj] += hv * sWhh[jy + jj][k];
    }

    float* h1n = g_h1[(t + 1) & 1];
    #pragma unroll
    for (int jj = 0; jj < 4; jj++) {
        int j = j0 + jy + jj;
        h1n[j * BB + b] = tanhf(acc[jj] + bih1[j] + bhh1[j]);
    }
}

// ---------------------------------------------------------------------------
// K2: h2cand = tanh(h1_new @ Wih2^T + b + h2 @ Whh2^T + b);
//     h2_new = u * h2cand + (1-u) * h2
// grid = H/4, block (128, 2), each y-half handles 2 output rows.
__global__ void __launch_bounds__(256) k_step2(
    const float* __restrict__ Wih2, const float* __restrict__ bih2,
    const float* __restrict__ Whh2, const float* __restrict__ bhh2,
    int t)
{
    __shared__ float sWa[4][HH];
    __shared__ float sWb[4][HH];
    int j0  = blockIdx.x * 4;
    int b   = threadIdx.x;
    int tid = threadIdx.y * 128 + threadIdx.x;

    for (int idx = tid; idx < 4 * HH; idx += 256) {
        int jj = idx >> 10, k = idx & 1023;
        sWa[jj][k] = Wih2[(j0 + jj) * HH + k];
        sWb[jj][k] = Whh2[(j0 + jj) * HH + k];
    }
    __syncthreads();

    const float* h1n = g_h1[(t + 1) & 1];
    const float* h2p = g_h2[t & 1];
    int jy = threadIdx.y * 2;
    float acc[2] = {0.f, 0.f};

    #pragma unroll 8
    for (int k = 0; k < HH; k++) {
        float av = h1n[k * BB + b];
        float bv = h2p[k * BB + b];
        #pragma unroll
        for (int jj = 0; jj < 2; jj++)
            acc[jj] += av * sWa[jy + jj][k] + bv * sWb[jy + jj][k];
    }

    float* h2n = g_h2[(t + 1) & 1];
    #pragma unroll
    for (int jj = 0; jj < 2; jj++) {
        int j = j0 + jy + jj;
        float cand  = tanhf(acc[jj] + bih2[j] + bhh2[j]);
        float uu    = g_u[j * BB + b];
        float hprev = h2p[j * BB + b];
        h2n[j * BB + b] = uu * cand + (1.f - uu) * hprev;
    }
}

// ---------------------------------------------------------------------------
// K3: blocks [0, H/4)      : u = sigmoid([h1,h2] @ Wg^T + bg)   (for NEXT step)
//     blocks [H/4, H/4+O/4): out = tanh(h1 Wo1^T+bo1) + tanh(h2 Wo2^T+bo2)
__global__ void __launch_bounds__(256) k_step3(
    const float* __restrict__ Wg,  const float* __restrict__ bg,
    const float* __restrict__ Wo1, const float* __restrict__ bo1,
    const float* __restrict__ Wo2, const float* __restrict__ bo2,
    float* __restrict__ out, int t)
{
    __shared__ float sA[4][HH];
    __shared__ float sB[4][HH];
    int b   = threadIdx.x;
    int tid = threadIdx.y * 128 + threadIdx.x;
    const float* h1n = g_h1[(t + 1) & 1];
    const float* h2n = g_h2[(t + 1) & 1];
    int jy = threadIdx.y * 2;

    if (blockIdx.x < HH / 4) {
        // ---- gate u ----
        int j0 = blockIdx.x * 4;
        for (int idx = tid; idx < 4 * HH; idx += 256) {
            int jj = idx >> 10, k = idx & 1023;
            sA[jj][k] = Wg[(j0 + jj) * (2 * HH) + k];
            sB[jj][k] = Wg[(j0 + jj) * (2 * HH) + HH + k];
        }
        __syncthreads();
        float acc[2] = {0.f, 0.f};
        #pragma unroll 8
        for (int k = 0; k < HH; k++) {
            float a = h1n[k * BB + b];
            float c = h2n[k * BB + b];
            #pragma unroll
            for (int jj = 0; jj < 2; jj++)
                acc[jj] += a * sA[jy + jj][k] + c * sB[jy + jj][k];
        }
        #pragma unroll
        for (int jj = 0; jj < 2; jj++) {
            int j = j0 + jy + jj;
            g_u[j * BB + b] = 1.f / (1.f + expf(-(acc[jj] + bg[j])));
        }
    } else {
        // ---- output heads ----
        int o0 = (blockIdx.x - HH / 4) * 4;
        for (int idx = tid; idx < 4 * HH; idx += 256) {
            int jj = idx >> 10, k = idx & 1023;
            sA[jj][k] = Wo1[(o0 + jj) * HH + k];
            sB[jj][k] = Wo2[(o0 + jj) * HH + k];
        }
        __syncthreads();
        float acc1[2] = {0.f, 0.f};
        float acc2[2] = {0.f, 0.f};
        #pragma unroll 8
        for (int k = 0; k < HH; k++) {
            float a = h1n[k * BB + b];
            float c = h2n[k * BB + b];
            #pragma unroll
            for (int jj = 0; jj < 2; jj++) {
                acc1[jj] += a * sA[jy + jj][k];
                acc2[jj] += c * sB[jy + jj][k];
            }
        }
        #pragma unroll
        for (int jj = 0; jj < 2; jj++) {
            int o = o0 + jy + jj;
            out[b * (TT * OO) + t * OO + o] =
                tanhf(acc1[jj] + bo1[o]) + tanhf(acc2[jj] + bo2[o]);
        }
    }
}

// ---------------------------------------------------------------------------
extern "C" void kernel_launch(void* const* d_in, const int* in_sizes, int n_in,
                              void* d_out, int out_size) {
    const float* x    = (const float*)d_in[0];
    const float* Wih1 = (const float*)d_in[1];
    const float* bih1 = (const float*)d_in[2];
    const float* Whh1 = (const float*)d_in[3];
    const float* bhh1 = (const float*)d_in[4];
    const float* Wih2 = (const float*)d_in[5];
    const float* bih2 = (const float*)d_in[6];
    const float* Whh2 = (const float*)d_in[7];
    const float* bhh2 = (const float*)d_in[8];
    const float* Wg   = (const float*)d_in[9];
    const float* bg   = (const float*)d_in[10];
    const float* Wo1  = (const float*)d_in[11];
    const float* bo1  = (const float*)d_in[12];
    const float* Wo2  = (const float*)d_in[13];
    const float* bo2  = (const float*)d_in[14];
    float* out = (float*)d_out;

    k_init<<<(HH * BB + 255) / 256, 256>>>();
    k_transpose_x<<<dim3(TT * II / 32, BB / 32), dim3(32, 32)>>>(x);

    for (int t = 0; t < TT; t++) {
        k_step1<<<HH / 8, dim3(128, 2)>>>(Wih1, bih1, Whh1, bhh1, t);
        k_step2<<<HH / 4, dim3(128, 2)>>>(Wih2, bih2, Whh2, bhh2, t);
        k_step3<<<HH / 4 + OO / 4, dim3(128, 2)>>>(Wg, bg, Wo1, bo1, Wo2, bo2,
                                                   out, t);
    }
}

// round 2
// speedup vs baseline: 2.7695x; 2.7695x over previous
#include <cuda_runtime.h>

#define BB 128
#define TT 256
#define II 64
#define HH 1024
#define OO 64
#define NCTA 148
#define KC 16

// ---------------- persistent device globals (no allocation) ----------------
__device__ float WAt[1088 * HH];        // [k][j]  k<64: Wih1, else Whh1
__device__ float WBt[2048 * HH];        // [k][j]  k<1024: Wih2, else Whh2
__device__ float WGt[2048 * HH];        // [k][j]  Wg
__device__ float WOt[HH * 128];         // [k][o]  o<64: Wo1, else Wo2
__device__ float g_xt[TT * II * BB];    // x transposed [t*I + i][b]
__device__ float g_h1[HH * BB];
__device__ float g_h2[HH * BB];
__device__ float g_u[HH * BB];
__device__ float partMain[9 * HH * BB]; // split-K partials  [slice][j][b]
__device__ float partHead[8 * 128 * BB];
__device__ unsigned g_bar;

// ---------------------------------------------------------------------------
__global__ void k_init() {
    int i = blockIdx.x * blockDim.x + threadIdx.x;
    if (i == 0) g_bar = 0u;
    if (i < HH * BB) {
        g_h1[i] = 0.f;
        g_h2[i] = 0.f;
        g_u[i]  = 1.f;
    }
}

// Transpose x[B][T*I] -> g_xt[T*I][B]
__global__ void k_transpose_x(const float* __restrict__ x) {
    __shared__ float tile[32][33];
    int n0 = blockIdx.x * 32;
    int m0 = blockIdx.y * 32;
    int tx = threadIdx.x, ty = threadIdx.y;
    tile[ty][tx] = x[(m0 + ty) * (TT * II) + n0 + tx];
    __syncthreads();
    g_xt[(n0 + ty) * BB + m0 + tx] = tile[tx][ty];
}

// Transpose all weights into [k][j] layouts (one-time per launch).
__global__ void k_prep(const float* __restrict__ Wih1, const float* __restrict__ Whh1,
                       const float* __restrict__ Wih2, const float* __restrict__ Whh2,
                       const float* __restrict__ Wg,
                       const float* __restrict__ Wo1, const float* __restrict__ Wo2)
{
    int stride = gridDim.x * blockDim.x;
    int t0 = blockIdx.x * blockDim.x + threadIdx.x;
    for (int i = t0; i < 1088 * HH; i += stride) {
        int k = i / HH, j = i % HH;
        WAt[i] = (k < II) ? Wih1[j * II + k] : Whh1[(size_t)j * HH + (k - II)];
    }
    for (int i = t0; i < 2048 * HH; i += stride) {
        int k = i / HH, j = i % HH;
        WBt[i] = (k < HH) ? Wih2[(size_t)j * HH + k]
                          : Whh2[(size_t)j * HH + (k - HH)];
        WGt[i] = Wg[(size_t)j * 2048 + k];
    }
    for (int i = t0; i < HH * 128; i += stride) {
        int k = i >> 7, o = i & 127;
        WOt[i] = (o < 64) ? Wo1[o * HH + k] : Wo2[(o - 64) * HH + k];
    }
}

// ---------------------------------------------------------------------------
// grid-wide barrier: monotonically increasing counter, all 148 CTAs resident.
__device__ __forceinline__ void gsync(unsigned &target) {
    __syncthreads();
    target += NCTA;
    if (threadIdx.x == 0) {
        __threadfence();
        atomicAdd(&g_bar, 1u);
        while (*(volatile unsigned*)&g_bar < target) { }
    }
    __syncthreads();
    __threadfence();  // acquire: invalidate L1 so fresh data is seen
}

// ---------------------------------------------------------------------------
__device__ __forceinline__ void load_chunk(
    const float* __restrict__ actA, int splitK, const float* __restrict__ actB,
    const float* __restrict__ Wt, int ldw, int j0, int kbase,
    float4 (&sAct)[2][KC][32], float2 (&sW)[2][KC][64], int buf, int tid)
{
    #pragma unroll
    for (int r = 0; r < 2; r++) {           // 512 float4 of activations
        int i = tid + r * 256;
        int kk = i >> 5;
        int b4 = i & 31;
        int k = kbase + kk;
        const float* s = (k < splitK) ? (actA + (size_t)k * BB)
                                      : (actB + (size_t)(k - splitK) * BB);
        sAct[buf][kk][b4] = *reinterpret_cast<const float4*>(s + b4 * 4);
    }
    #pragma unroll
    for (int r = 0; r < 2; r++) {           // 512 float2 of weights, splatted
        int i = tid + r * 256;
        int kk = i >> 5;
        int j2 = (i & 31) * 2;
        float2 w = *reinterpret_cast<const float2*>(
            Wt + (size_t)(kbase + kk) * ldw + j0 + j2);
        sW[buf][kk][j2]     = make_float2(w.x, w.x);
        sW[buf][kk][j2 + 1] = make_float2(w.y, w.y);
    }
}

// One split-K GEMM work unit: C[64 j][128 b] over chunks [c0, c1) of 16 k.
// Thread (tx,ty): 4 batches (tx*4..) x 8 outputs (ty*8..), f32x2 FMA.
__device__ __forceinline__ void gemm_unit(
    const float* actA, int splitK, const float* actB,
    const float* Wt, int ldw, int j0,
    int c0, int c1, float* dst,
    float4 (&sAct)[2][KC][32], float2 (&sW)[2][KC][64], int tid)
{
    int tx = tid & 31, ty = tid >> 5;
    unsigned long long a0[8], a1[8];
    #pragma unroll
    for (int jj = 0; jj < 8; jj++) { a0[jj] = 0ull; a1[jj] = 0ull; }

    load_chunk(actA, splitK, actB, Wt, ldw, j0, c0 * KC, sAct, sW, 0, tid);
    __syncthreads();
    int buf = 0;
    for (int c = c0; c < c1; c++) {
        if (c + 1 < c1)
            load_chunk(actA, splitK, actB, Wt, ldw, j0, (c + 1) * KC,
                       sAct, sW, buf ^ 1, tid);
        #pragma unroll 4
        for (int kk = 0; kk < KC; kk++) {
            ulonglong2 av =
                *reinterpret_cast<const ulonglong2*>(&sAct[buf][kk][tx]);
            #pragma unroll
            for (int jj = 0; jj < 8; jj++) {
                unsigned long long w = *reinterpret_cast<const unsigned long long*>(
                    &sW[buf][kk][ty * 8 + jj]);
                asm("fma.rn.f32x2 %0, %1, %2, %0;"
                    : "+l"(a0[jj]) : "l"(w), "l"(av.x));
                asm("fma.rn.f32x2 %0, %1, %2, %0;"
                    : "+l"(a1[jj]) : "l"(w), "l"(av.y));
            }
        }
        __syncthreads();
        buf ^= 1;
    }
    #pragma unroll
    for (int jj = 0; jj < 8; jj++) {
        float2 lo = *reinterpret_cast<float2*>(&a0[jj]);
        float2 hi = *reinterpret_cast<float2*>(&a1[jj]);
        *reinterpret_cast<float4*>(dst + (size_t)(ty * 8 + jj) * BB + tx * 4)
            = make_float4(lo.x, lo.y, hi.x, hi.y);
    }
}

// ---------------------------------------------------------------------------
__global__ void __launch_bounds__(256, 1) k_rnn(
    const float* __restrict__ bih1, const float* __restrict__ bhh1,
    const float* __restrict__ bih2, const float* __restrict__ bhh2,
    const float* __restrict__ bg,
    const float* __restrict__ bo1, const float* __restrict__ bo2,
    float* __restrict__ out)
{
    __shared__ float4 sAct[2][KC][32];
    __shared__ float2 sW[2][KC][64];
    const int tid = threadIdx.x;
    const int u = blockIdx.x;
    unsigned target = 0;

    for (int t = 0; t < TT; t++) {
        // ---- phase A: pre-act of h1 = x_t@Wih1^T + h1@Whh1^T (K=1088) ----
        if (u < 144) {
            int jt = u & 15, ks = u >> 4;                  // 16 x 9
            int c0 = (ks * 68) / 9, c1 = ((ks + 1) * 68) / 9;
            gemm_unit(g_xt + (size_t)t * II * BB, II, g_h1,
                      WAt, HH, jt * 64, c0, c1,
                      partMain + (size_t)ks * (HH * BB) + jt * 64 * BB,
                      sAct, sW, tid);
        }
        gsync(target);
        // ---- reduce A: h1 = tanh(sum + biases) ----
        for (int i = u * 256 + tid; i < HH * BB; i += NCTA * 256) {
            int j = i >> 7;
            float s = bih1[j] + bhh1[j];
            #pragma unroll
            for (int ss = 0; ss < 9; ss++) s += partMain[ss * (HH * BB) + i];
            g_h1[i] = tanhf(s);
        }
        gsync(target);
        // ---- phase B: pre-act of h2cand (K=2048: h1|h2) ----
        if (u < 144) {
            int jt = u & 15, ks = u >> 4;
            int c0 = (ks * 128) / 9, c1 = ((ks + 1) * 128) / 9;
            gemm_unit(g_h1, HH, g_h2, WBt, HH, jt * 64, c0, c1,
                      partMain + (size_t)ks * (HH * BB) + jt * 64 * BB,
                      sAct, sW, tid);
        }
        gsync(target);
        // ---- reduce B: h2 = u*tanh(sum+b) + (1-u)*h2 ----
        for (int i = u * 256 + tid; i < HH * BB; i += NCTA * 256) {
            int j = i >> 7;
            float s = bih2[j] + bhh2[j];
            #pragma unroll
            for (int ss = 0; ss < 9; ss++) s += partMain[ss * (HH * BB) + i];
            float cand = tanhf(s);
            float uu = g_u[i];
            g_h2[i] = uu * cand + (1.f - uu) * g_h2[i];
        }
        gsync(target);
        // ---- phase C: gate (128 units) + output heads (16 units) ----
        if (u < 128) {
            int jt = u & 15, ks = u >> 4;                  // ks 0..7
            gemm_unit(g_h1, HH, g_h2, WGt, HH, jt * 64, ks * 16, ks * 16 + 16,
                      partMain + (size_t)ks * (HH * BB) + jt * 64 * BB,
                      sAct, sW, tid);
        } else if (u < 144) {
            int uu = u - 128;
            int head = uu >> 3, ks = uu & 7;               // K=1024: 8x8 chunks
            const float* act = head ? g_h2 : g_h1;
            gemm_unit(act, 1 << 30, act, WOt, 128, head * 64,
                      ks * 8, ks * 8 + 8,
                      partHead + (size_t)ks * (128 * BB) + head * 64 * BB,
                      sAct, sW, tid);
        }
        gsync(target);
        // ---- reduce C: u = sigmoid(sum+bg); out = tanh+tanh ----
        for (int i = u * 256 + tid; i < HH * BB; i += NCTA * 256) {
            int j = i >> 7;
            float s = bg[j];
            #pragma unroll
            for (int ss = 0; ss < 8; ss++) s += partMain[ss * (HH * BB) + i];
            g_u[i] = 1.f / (1.f + expf(-s));
        }
        for (int i = u * 256 + tid; i < OO * BB; i += NCTA * 256) {
            int o = i >> 7, b = i & 127;
            float s1 = bo1[o], s2 = bo2[o];
            #pragma unroll
            for (int ss = 0; ss < 8; ss++) {
                s1 += partHead[ss * (128 * BB) + o * BB + b];
                s2 += partHead[ss * (128 * BB) + (o + 64) * BB + b];
            }
            out[(size_t)b * (TT * OO) + t * OO + o] = tanhf(s1) + tanhf(s2);
        }
        gsync(target);
    }
}

// ---------------------------------------------------------------------------
extern "C" void kernel_launch(void* const* d_in, const int* in_sizes, int n_in,
                              void* d_out, int out_size) {
    const float* x    = (const float*)d_in[0];
    const float* Wih1 = (const float*)d_in[1];
    const float* bih1 = (const float*)d_in[2];
    const float* Whh1 = (const float*)d_in[3];
    const float* bhh1 = (const float*)d_in[4];
    const float* Wih2 = (const float*)d_in[5];
    const float* bih2 = (const float*)d_in[6];
    const float* Whh2 = (const float*)d_in[7];
    const float* bhh2 = (const float*)d_in[8];
    const float* Wg   = (const float*)d_in[9];
    const float* bg   = (const float*)d_in[10];
    const float* Wo1  = (const float*)d_in[11];
    const float* bo1  = (const float*)d_in[12];
    const float* Wo2  = (const float*)d_in[13];
    const float* bo2  = (const float*)d_in[14];
    float* out = (float*)d_out;

    k_init<<<(HH * BB + 255) / 256, 256>>>();
    k_transpose_x<<<dim3(TT * II / 32, BB / 32), dim3(32, 32)>>>(x);
    k_prep<<<512, 256>>>(Wih1, Whh1, Wih2, Whh2, Wg, Wo1, Wo2);
    k_rnn<<<NCTA, 256>>>(bih1, bhh1, bih2, bhh2, bg, bo1, bo2, out);
}